// round 16
// baseline (speedup 1.0000x reference)
#include <cuda_runtime.h>
#include <cuda_bf16.h>
#include <cuda_fp16.h>
#include <math_constants.h>
#include <cstdint>

#define SEQ 2048
#define DM  512
#define NB  2
#define NH  8
#define DH  64
#define MROWS (NB*SEQ)   // 4096

// split activations, head-split layout [b][h][n][dh]
__device__ __align__(16) __nv_bfloat16 g_Qh[NB*NH*SEQ*DH], g_Ql[NB*NH*SEQ*DH];
__device__ __align__(16) __nv_bfloat16 g_Kh[NB*NH*SEQ*DH], g_Kl[NB*NH*SEQ*DH];
__device__ __align__(16) __half       g_Vh[NB*NH*SEQ*DH];
__device__ __align__(16) float        g_qn[NB*NH*SEQ], g_kn[NB*NH*SEQ];
// GEMM operands
__device__ __align__(16) __nv_bfloat16 g_xh[MROWS*DM], g_xl[MROWS*DM];
__device__ __align__(16) __nv_bfloat16 g_Wh[4*DM*DM],  g_Wl[4*DM*DM];
__device__ __align__(16) __nv_bfloat16 g_Oh[MROWS*DM], g_Ol[MROWS*DM];
// split-KV partial scratch: 256 jobs x (128x64 accO fp32) + (128 x {m,l})
__device__ __align__(16) float g_pO[256*8192];
__device__ __align__(16) float g_pml[256*256];

#define LOG2E 1.4426950408889634f

// ---------------- helpers ----------------
__device__ __forceinline__ uint32_t smem_u32(const void* p) {
    uint32_t a;
    asm("{ .reg .u64 t; cvta.to.shared.u64 t, %1; cvt.u32.u64 %0, t; }" : "=r"(a) : "l"(p));
    return a;
}
__device__ __forceinline__ float ex2f(float x) {
    float y; asm("ex2.approx.f32 %0, %1;" : "=f"(y) : "f"(x)); return y;
}
#define CPA16(dst, src) asm volatile("cp.async.cg.shared.global [%0], [%1], 16;" :: "r"(dst), "l"(src) : "memory")
#define CP_COMMIT()     asm volatile("cp.async.commit_group;" ::: "memory")
#define CP_WAIT1()      asm volatile("cp.async.wait_group 1;" ::: "memory")

__device__ __forceinline__ void ldm_x4(uint32_t* r, uint32_t addr) {
    asm volatile("ldmatrix.sync.aligned.m8n8.x4.shared.b16 {%0,%1,%2,%3}, [%4];"
                 : "=r"(r[0]), "=r"(r[1]), "=r"(r[2]), "=r"(r[3]) : "r"(addr));
}
__device__ __forceinline__ void ldm_x4_trans(uint32_t* r, uint32_t addr) {
    asm volatile("ldmatrix.sync.aligned.m8n8.x4.trans.shared.b16 {%0,%1,%2,%3}, [%4];"
                 : "=r"(r[0]), "=r"(r[1]), "=r"(r[2]), "=r"(r[3]) : "r"(addr));
}
__device__ __forceinline__ void mma_bf16(float* d, const uint32_t* a, const uint32_t* b) {
    asm volatile("mma.sync.aligned.m16n8k16.row.col.f32.bf16.bf16.f32 "
                 "{%0,%1,%2,%3}, {%4,%5,%6,%7}, {%8,%9}, {%0,%1,%2,%3};"
                 : "+f"(d[0]), "+f"(d[1]), "+f"(d[2]), "+f"(d[3])
                 : "r"(a[0]), "r"(a[1]), "r"(a[2]), "r"(a[3]), "r"(b[0]), "r"(b[1]));
}
__device__ __forceinline__ void mma_f16(float* d, const uint32_t* a, const uint32_t* b) {
    asm volatile("mma.sync.aligned.m16n8k16.row.col.f32.f16.f16.f32 "
                 "{%0,%1,%2,%3}, {%4,%5,%6,%7}, {%8,%9}, {%0,%1,%2,%3};"
                 : "+f"(d[0]), "+f"(d[1]), "+f"(d[2]), "+f"(d[3])
                 : "r"(a[0]), "r"(a[1]), "r"(a[2]), "r"(a[3]), "r"(b[0]), "r"(b[1]));
}
__device__ __forceinline__ void split2(float a, float b, uint32_t& h, uint32_t& l) {
    __nv_bfloat16 ha = __float2bfloat16(a), hb = __float2bfloat16(b);
    __nv_bfloat16 la = __float2bfloat16(a - __bfloat162float(ha));
    __nv_bfloat16 lb = __float2bfloat16(b - __bfloat162float(hb));
    __nv_bfloat162 H; H.x = ha; H.y = hb;
    __nv_bfloat162 L; L.x = la; L.y = lb;
    h = *(uint32_t*)&H; l = *(uint32_t*)&L;
}
__device__ __forceinline__ uint32_t packh2(float a, float b) {
    __half2 h = __floats2half2_rn(a, b);
    return *(uint32_t*)&h;
}

// ---------------- conversions ----------------
__global__ void __launch_bounds__(256) cvt_x_kernel(const float* __restrict__ src, int n) {
    int i = (blockIdx.x * 256 + threadIdx.x) * 4;
    if (i >= n) return;
    float4 v = *(const float4*)(src + i);
    float vv[4] = {v.x, v.y, v.z, v.w};
#pragma unroll
    for (int k = 0; k < 4; k++) {
        __nv_bfloat16 h = __float2bfloat16(vv[k]);
        g_xh[i + k] = h;
        g_xl[i + k] = __float2bfloat16(vv[k] - __bfloat162float(h));
    }
}
__global__ void __launch_bounds__(256) cvt_w_kernel(const float* __restrict__ w0,
                                                    const float* __restrict__ w1,
                                                    const float* __restrict__ w2,
                                                    const float* __restrict__ w3) {
    const int z = blockIdx.y;
    const float* src = (z == 0) ? w0 : (z == 1) ? w1 : (z == 2) ? w2 : w3;
    int i = (blockIdx.x * 256 + threadIdx.x) * 4;
    __nv_bfloat16* dh = g_Wh + (size_t)z * DM * DM;
    __nv_bfloat16* dl = g_Wl + (size_t)z * DM * DM;
    float4 v = *(const float4*)(src + i);
    float vv[4] = {v.x, v.y, v.z, v.w};
#pragma unroll
    for (int k = 0; k < 4; k++) {
        __nv_bfloat16 h = __float2bfloat16(vv[k]);
        dh[i + k] = h;
        dl[i + k] = __float2bfloat16(vv[k] - __bfloat162float(h));
    }
}

// ---------------- split-bf16 GEMM via mma.sync, 128x64 tile, cp.async 2-stage ----------------
#define ASTR 40
#define G_A_BUF (128*ASTR*2)               // 10240 B
#define G_B_BUF (64*ASTR*2)                // 5120 B
#define GEMM_STAGE_B (2*G_A_BUF + 2*G_B_BUF)  // 30720 B
#define GEMM_SMEM    (2*GEMM_STAGE_B)      // 61440 B

template<int MODE>
__global__ void __launch_bounds__(256) mma_gemm_kernel(float* __restrict__ outp) {
    extern __shared__ __align__(16) char gsm[];
    const int t = threadIdx.x, lane = t & 31, w = t >> 5;
    const int wm = w & 3, wn = w >> 2;           // warp tile 32x32
    const int m0 = blockIdx.y * 128, j0 = blockIdx.x * 64;
    const int wsel = (MODE == 0) ? (int)blockIdx.z : 3;

    const __nv_bfloat16* Ahp = (MODE == 0) ? g_xh : g_Oh;
    const __nv_bfloat16* Alp = (MODE == 0) ? g_xl : g_Ol;
    const __nv_bfloat16* Whp = g_Wh + (size_t)wsel * DM * DM;
    const __nv_bfloat16* Wlp = g_Wl + (size_t)wsel * DM * DM;

    const uint32_t smb = smem_u32(gsm);

    float acc[2][4][4];
#pragma unroll
    for (int mt = 0; mt < 2; mt++)
#pragma unroll
        for (int nt = 0; nt < 4; nt++)
#pragma unroll
            for (int e = 0; e < 4; e++) acc[mt][nt][e] = 0.f;

    const int arow = wm*32 + (lane & 15);
    const int boff = ((lane >> 4) & 1) * 8;
    const int brow = wn*32 + (lane & 7) + ((lane >> 4) & 1) * 8;
    const int bcol = ((lane >> 3) & 1) * 8;

    // prologue: slab 0 -> stage 0
    {
#pragma unroll
        for (int p = 0; p < 2; p++) {
            int id = t + 256 * p;
            int r = id >> 2, cc = id & 3;
            uint32_t off = (uint32_t)(r * ASTR * 2 + cc * 16);
            const size_t ga = (size_t)(m0 + r) * DM + cc*8;
            CPA16(smb + off,           Ahp + ga);
            CPA16(smb + G_A_BUF + off, Alp + ga);
        }
        {
            int r = t >> 2, cc = t & 3;
            uint32_t off = (uint32_t)(r * ASTR * 2 + cc * 16);
            const size_t gb = (size_t)(j0 + r) * DM + cc*8;
            CPA16(smb + 2*G_A_BUF + off,           Whp + gb);
            CPA16(smb + 2*G_A_BUF + G_B_BUF + off, Wlp + gb);
        }
        CP_COMMIT();
    }

    for (int s = 0; s < DM/32; s++) {
        const int st = s & 1;
        __syncthreads();
        if (s + 1 < DM/32) {
            const uint32_t base = smb + (st ^ 1) * GEMM_STAGE_B;
#pragma unroll
            for (int p = 0; p < 2; p++) {
                int id = t + 256 * p;
                int r = id >> 2, cc = id & 3;
                uint32_t off = (uint32_t)(r * ASTR * 2 + cc * 16);
                const size_t ga = (size_t)(m0 + r) * DM + (s+1)*32 + cc*8;
                CPA16(base + off,           Ahp + ga);
                CPA16(base + G_A_BUF + off, Alp + ga);
            }
            {
                int r = t >> 2, cc = t & 3;
                uint32_t off = (uint32_t)(r * ASTR * 2 + cc * 16);
                const size_t gb = (size_t)(j0 + r) * DM + (s+1)*32 + cc*8;
                CPA16(base + 2*G_A_BUF + off,           Whp + gb);
                CPA16(base + 2*G_A_BUF + G_B_BUF + off, Wlp + gb);
            }
        }
        CP_COMMIT();
        CP_WAIT1();
        __syncthreads();

        const __nv_bfloat16* sAh = (const __nv_bfloat16*)(gsm + st * GEMM_STAGE_B);
        const __nv_bfloat16* sAl = sAh + 128*ASTR;
        const __nv_bfloat16* sBh = sAl + 128*ASTR;
        const __nv_bfloat16* sBl = sBh + 64*ASTR;

#pragma unroll
        for (int ks = 0; ks < 2; ks++) {
            uint32_t ah[2][4], al[2][4];
#pragma unroll
            for (int mt = 0; mt < 2; mt++) {
                ldm_x4(ah[mt], smem_u32(&sAh[(arow + mt*16)*ASTR + ks*16 + boff]));
                ldm_x4(al[mt], smem_u32(&sAl[(arow + mt*16)*ASTR + ks*16 + boff]));
            }
            uint32_t bh[4][2], bl[4][2];
#pragma unroll
            for (int pr = 0; pr < 2; pr++) {
                uint32_t r4[4];
                ldm_x4(r4, smem_u32(&sBh[(brow + pr*16)*ASTR + ks*16 + bcol]));
                bh[2*pr][0] = r4[0]; bh[2*pr][1] = r4[1];
                bh[2*pr+1][0] = r4[2]; bh[2*pr+1][1] = r4[3];
                ldm_x4(r4, smem_u32(&sBl[(brow + pr*16)*ASTR + ks*16 + bcol]));
                bl[2*pr][0] = r4[0]; bl[2*pr][1] = r4[1];
                bl[2*pr+1][0] = r4[2]; bl[2*pr+1][1] = r4[3];
            }
#pragma unroll
            for (int mt = 0; mt < 2; mt++)
#pragma unroll
                for (int nt = 0; nt < 4; nt++) {
                    mma_bf16(acc[mt][nt], ah[mt], bh[nt]);
                    mma_bf16(acc[mt][nt], ah[mt], bl[nt]);
                    mma_bf16(acc[mt][nt], al[mt], bh[nt]);
                }
        }
    }

    const int gid = lane >> 2, tig = lane & 3;
#pragma unroll
    for (int mt = 0; mt < 2; mt++) {
#pragma unroll
        for (int nt = 0; nt < 4; nt++) {
            const int mrow = m0 + wm*32 + mt*16 + gid;
            const int jcol = j0 + wn*32 + nt*8 + tig*2;
            if (MODE == 1) {
                *(float2*)(outp + (size_t)mrow * DM + jcol)     = make_float2(acc[mt][nt][0], acc[mt][nt][1]);
                *(float2*)(outp + (size_t)(mrow+8) * DM + jcol) = make_float2(acc[mt][nt][2], acc[mt][nt][3]);
            } else {
                const int hh = j0 >> 6, d = jcol & (DH-1);
                const int b0r = mrow >> 11, n0r = mrow & (SEQ-1);
                const size_t base = ((size_t)(b0r*NH + hh)*SEQ + n0r)*DH + d;
                if (blockIdx.z == 2) {          // V: single fp16
                    *(uint32_t*)(g_Vh + base)        = packh2(acc[mt][nt][0], acc[mt][nt][1]);
                    *(uint32_t*)(g_Vh + base + 8*DH) = packh2(acc[mt][nt][2], acc[mt][nt][3]);
                } else {
                    __nv_bfloat16* dsh = (blockIdx.z == 0) ? g_Qh : g_Kh;
                    __nv_bfloat16* dsl = (blockIdx.z == 0) ? g_Ql : g_Kl;
                    uint32_t ph_, pl_;
                    split2(acc[mt][nt][0], acc[mt][nt][1], ph_, pl_);
                    *(uint32_t*)(dsh + base) = ph_;
                    *(uint32_t*)(dsl + base) = pl_;
                    split2(acc[mt][nt][2], acc[mt][nt][3], ph_, pl_);
                    *(uint32_t*)(dsh + base + 8*DH) = ph_;
                    *(uint32_t*)(dsl + base + 8*DH) = pl_;
                }
            }
        }
    }

    // ---- fused exact row norms for Q (z=0) and K (z=1) ----
    if (MODE == 0 && blockIdx.z < 2) {
        float* np = (blockIdx.z == 0) ? g_qn : g_kn;
        float* spart = (float*)gsm;
        __syncthreads();
#pragma unroll
        for (int mt = 0; mt < 2; mt++) {
            float s0 = 0.f, s1 = 0.f;
#pragma unroll
            for (int nt = 0; nt < 4; nt++) {
                s0 = fmaf(acc[mt][nt][0], acc[mt][nt][0], fmaf(acc[mt][nt][1], acc[mt][nt][1], s0));
                s1 = fmaf(acc[mt][nt][2], acc[mt][nt][2], fmaf(acc[mt][nt][3], acc[mt][nt][3], s1));
            }
            s0 += __shfl_xor_sync(0xffffffffu, s0, 1);
            s0 += __shfl_xor_sync(0xffffffffu, s0, 2);
            s1 += __shfl_xor_sync(0xffffffffu, s1, 1);
            s1 += __shfl_xor_sync(0xffffffffu, s1, 2);
            if (tig == 0) {
                spart[((w*2 + mt)*2 + 0)*8 + gid] = s0;
                spart[((w*2 + mt)*2 + 1)*8 + gid] = s1;
            }
        }
        __syncthreads();
        if (w < 4) {
            const int mt = lane >> 4, half = (lane >> 3) & 1, g8 = lane & 7;
            const float s = spart[((w*2 + mt)*2 + half)*8 + g8]
                          + spart[(((w+4)*2 + mt)*2 + half)*8 + g8];
            const int mrow = m0 + w*32 + mt*16 + half*8 + g8;
            const int hh = j0 >> 6;
            const int b0r = mrow >> 11, n0r = mrow & (SEQ-1);
            np[(size_t)(b0r*NH + hh)*SEQ + n0r] = s;
        }
    }
}

// ---------------- mma.sync hyperbolic flash attention: 128-query CTAs, 8 warps ----------------
// log2-domain softmax; V single fp16; double-buffered K/V/kn stage shared by 8 warps.
#define KSTR 72
#define TILE_B (64*KSTR*2)                 // 9216 B (one 64-row bf16/fp16 buffer)
#define QSZ    (4*TILE_B)                  // 36864 B (Qh, Ql for 128 rows)
#define STAGE_B (3*TILE_B + 256)           // Kh, Kl, V, kn = 27904 B
#define ATTN_SMEM (QSZ + 2*STAGE_B)        // 92672 B
#define PRUNE_MARGIN 29.0f                 // log2 units

__global__ void __launch_bounds__(256, 2) attn_mma_kernel(const float* __restrict__ p_logc,
                                                          const float* __restrict__ p_logb) {
    extern __shared__ __align__(16) char smraw[];
    __nv_bfloat16* Qh = (__nv_bfloat16*)smraw;                  // 128 x KSTR
    __nv_bfloat16* Ql = (__nv_bfloat16*)(smraw + 2*TILE_B);     // 128 x KSTR
    const uint32_t smb = smem_u32(smraw);

    const int t = threadIdx.x, lane = t & 31, w = t >> 5;       // w in 0..7
    const int jx = (int)blockIdx.x;                             // 0..23
    const int h = blockIdx.y, b = blockIdx.z;
    const int bh = b*NH + h;

    // jobs: jx<16 -> partial (qt 15..8, two halves); jx>=16 -> full (qt 7..0)
    int qt, k0, k1, sp;
    bool partial;
    if (jx < 16) {
        qt = 15 - (jx >> 1);
        sp = jx & 1;
        const int mid = qt + 1;
        k0 = sp ? mid : 0;
        k1 = sp ? (2*qt + 2) : mid;
        partial = true;
    } else {
        qt = 23 - jx; k0 = 0; k1 = 2*qt + 2; sp = 0; partial = false;
    }
    const int nk = k1 - k0;

    const float c    = log1pf(__expf(*p_logc));
    const float beta = log1pf(__expf(*p_logb)) + 0.5f;
    const float nbl  = -beta * LOG2E;

    const int gid = lane >> 2, tig = lane & 3;

    // Q tile: 128 rows
    const size_t qoff = ((size_t)bh*SEQ + qt*128) * DH;
#pragma unroll
    for (int p = 0; p < 4; p++) {
        int id = t + 256*p;
        int r = id >> 3, cc = id & 7;
        *(uint4*)&Qh[r*KSTR + cc*8] = *(const uint4*)(g_Qh + qoff + r*64 + cc*8);
        *(uint4*)&Ql[r*KSTR + cc*8] = *(const uint4*)(g_Ql + qoff + r*64 + cc*8);
    }
    const float qn0 = g_qn[(size_t)bh*SEQ + qt*128 + w*16 + gid];
    const float qn1 = g_qn[(size_t)bh*SEQ + qt*128 + w*16 + gid + 8];

    const int arow  = w*16 + (lane & 15);
    const int acsel = ((lane >> 4) & 1) * 8;
    const int brow  = (lane & 7) + ((lane >> 4) & 1) * 8;
    const int bcol  = ((lane >> 3) & 1) * 8;

    float accO[8][4];
#pragma unroll
    for (int nt = 0; nt < 8; nt++)
#pragma unroll
        for (int e = 0; e < 4; e++) accO[nt][e] = 0.f;
    float m0 = -CUDART_INF_F, m1 = -CUDART_INF_F, l0 = 0.f, l1 = 0.f;

    // prologue: tile (k1-1) -> stage 0 (diagonal-first order)
    {
        const size_t koff = ((size_t)bh*SEQ + (k1-1)*64) * DH;
        const uint32_t base = smb + QSZ;
#pragma unroll
        for (int p = 0; p < 2; p++) {
            int id = t + 256*p;
            int r = id >> 3, cc = id & 7;
            uint32_t off = (uint32_t)(r*KSTR*2 + cc*16);
            CPA16(base + off,            g_Kh + koff + r*64 + cc*8);
            CPA16(base + TILE_B + off,   g_Kl + koff + r*64 + cc*8);
            CPA16(base + 2*TILE_B + off, g_Vh + koff + r*64 + cc*8);
        }
        if (t < 16) CPA16(base + 3*TILE_B + t*16, g_kn + (size_t)bh*SEQ + (k1-1)*64 + t*4);
        CP_COMMIT();
    }

    for (int i = 0; i < nk; i++) {
        const int kt = k1 - 1 - i;
        const int st = i & 1;
        __syncthreads();

        if (i + 1 < nk) {
            const size_t koff = ((size_t)bh*SEQ + (kt-1)*64) * DH;
            const uint32_t base = smb + QSZ + (st ^ 1) * STAGE_B;
#pragma unroll
            for (int p = 0; p < 2; p++) {
                int id = t + 256*p;
                int r = id >> 3, cc = id & 7;
                uint32_t off = (uint32_t)(r*KSTR*2 + cc*16);
                CPA16(base + off,            g_Kh + koff + r*64 + cc*8);
                CPA16(base + TILE_B + off,   g_Kl + koff + r*64 + cc*8);
                CPA16(base + 2*TILE_B + off, g_Vh + koff + r*64 + cc*8);
            }
            if (t < 16) CPA16(base + 3*TILE_B + t*16, g_kn + (size_t)bh*SEQ + (kt-1)*64 + t*4);
        }
        CP_COMMIT();
        CP_WAIT1();
        __syncthreads();

        const char* stg = smraw + QSZ + st*STAGE_B;
        const __nv_bfloat16* Kh = (const __nv_bfloat16*)stg;
        const __nv_bfloat16* Kl = (const __nv_bfloat16*)(stg + TILE_B);
        const __half*        Vp = (const __half*)(stg + 2*TILE_B);
        const float*         kn = (const float*)(stg + 3*TILE_B);

        // ---- S = Q K^T (per-pr B-frag loads to cap register pressure) ----
        float accS[8][4];
#pragma unroll
        for (int nt = 0; nt < 8; nt++)
#pragma unroll
            for (int e = 0; e < 4; e++) accS[nt][e] = 0.f;
#pragma unroll
        for (int ks = 0; ks < 4; ks++) {
            uint32_t ah[4], al[4];
            ldm_x4(ah, smem_u32(&Qh[arow*KSTR + ks*16 + acsel]));
            ldm_x4(al, smem_u32(&Ql[arow*KSTR + ks*16 + acsel]));
#pragma unroll
            for (int pr = 0; pr < 4; pr++) {
                uint32_t rh[4], rl[4];
                ldm_x4(rh, smem_u32(&Kh[(brow + pr*16)*KSTR + ks*16 + bcol]));
                ldm_x4(rl, smem_u32(&Kl[(brow + pr*16)*KSTR + ks*16 + bcol]));
                mma_bf16(accS[2*pr],   ah, rh);
                mma_bf16(accS[2*pr],   ah, rl);
                mma_bf16(accS[2*pr],   al, rh);
                mma_bf16(accS[2*pr+1], ah, rh + 2);
                mma_bf16(accS[2*pr+1], ah, rl + 2);
                mma_bf16(accS[2*pr+1], al, rh + 2);
            }
        }

        // ---- log2-domain scores ----
#pragma unroll
        for (int nt = 0; nt < 8; nt++) {
            const int lc = nt*8 + tig*2;
            const float kn0 = kn[lc], kn1 = kn[lc + 1];
            float sv[4] = {accS[nt][0], accS[nt][1], accS[nt][2], accS[nt][3]};
            float qq[4] = {qn0, qn0, qn1, qn1};
            float kk[4] = {kn0, kn1, kn0, kn1};
#pragma unroll
            for (int e = 0; e < 4; e++) {
                float a    = qq[e] + kk[e];
                float diff = fmaxf(fmaf(-2.f, sv[e], a), 1e-8f);
                float prod = diff * fmaf(c, a, 1.f);
                accS[nt][e] = nbl * (prod * rsqrtf(prod));
            }
        }
        // ---- causal mask: warp-uniform need test ----
        if (kt*64 + 63 > qt*128 + w*16) {
            const int grow0 = qt*128 + w*16 + gid, grow1 = grow0 + 8;
#pragma unroll
            for (int nt = 0; nt < 8; nt++) {
                const int gc0 = kt*64 + nt*8 + tig*2, gc1 = gc0 + 1;
                accS[nt][0] = (gc0 <= grow0) ? accS[nt][0] : -CUDART_INF_F;
                accS[nt][1] = (gc1 <= grow0) ? accS[nt][1] : -CUDART_INF_F;
                accS[nt][2] = (gc0 <= grow1) ? accS[nt][2] : -CUDART_INF_F;
                accS[nt][3] = (gc1 <= grow1) ? accS[nt][3] : -CUDART_INF_F;
            }
        }

        // ---- row maxes ----
        float rmax0 = -CUDART_INF_F, rmax1 = -CUDART_INF_F;
#pragma unroll
        for (int nt = 0; nt < 8; nt++) {
            rmax0 = fmaxf(rmax0, fmaxf(accS[nt][0], accS[nt][1]));
            rmax1 = fmaxf(rmax1, fmaxf(accS[nt][2], accS[nt][3]));
        }
        rmax0 = fmaxf(rmax0, __shfl_xor_sync(0xffffffffu, rmax0, 1));
        rmax0 = fmaxf(rmax0, __shfl_xor_sync(0xffffffffu, rmax0, 2));
        rmax1 = fmaxf(rmax1, __shfl_xor_sync(0xffffffffu, rmax1, 1));
        rmax1 = fmaxf(rmax1, __shfl_xor_sync(0xffffffffu, rmax1, 2));

        // ---- prune (also skips fully-masked half-tiles) ----
        const bool keep = (rmax0 > m0 - PRUNE_MARGIN) || (rmax1 > m1 - PRUNE_MARGIN);
        if (!__any_sync(0xffffffffu, keep)) continue;

        // ---- rescale only if max advanced ----
        {
            const float mn0 = fmaxf(m0, rmax0), mn1 = fmaxf(m1, rmax1);
            const bool ch = (mn0 != m0) || (mn1 != m1);
            if (__any_sync(0xffffffffu, ch)) {
                const float sc0 = ex2f(m0 - mn0), sc1 = ex2f(m1 - mn1);
#pragma unroll
                for (int nt = 0; nt < 8; nt++) {
                    accO[nt][0] *= sc0; accO[nt][1] *= sc0;
                    accO[nt][2] *= sc1; accO[nt][3] *= sc1;
                }
                l0 *= sc0; l1 *= sc1;
                m0 = mn0; m1 = mn1;
            }
        }

        // ---- weights ----
        float rs0 = 0.f, rs1 = 0.f;
#pragma unroll
        for (int nt = 0; nt < 8; nt++) {
            float w0 = ex2f(accS[nt][0] - m0);
            float w1 = ex2f(accS[nt][1] - m0);
            float w2 = ex2f(accS[nt][2] - m1);
            float w3 = ex2f(accS[nt][3] - m1);
            accS[nt][0] = w0; accS[nt][1] = w1; accS[nt][2] = w2; accS[nt][3] = w3;
            rs0 += w0 + w1; rs1 += w2 + w3;
        }
        rs0 += __shfl_xor_sync(0xffffffffu, rs0, 1);
        rs0 += __shfl_xor_sync(0xffffffffu, rs0, 2);
        rs1 += __shfl_xor_sync(0xffffffffu, rs1, 1);
        rs1 += __shfl_xor_sync(0xffffffffu, rs1, 2);
        l0 += rs0; l1 += rs1;

        // ---- O += P V (single fp16 V; per-pr V-frag loads) ----
        const int vrow = ((lane >> 3) & 1) * 8 + (lane & 7);
        const int vcol = ((lane >> 4) & 1) * 8;
#pragma unroll
        for (int ks = 0; ks < 4; ks++) {
            uint32_t ph[4];
            ph[0] = packh2(accS[2*ks][0],   accS[2*ks][1]);
            ph[1] = packh2(accS[2*ks][2],   accS[2*ks][3]);
            ph[2] = packh2(accS[2*ks+1][0], accS[2*ks+1][1]);
            ph[3] = packh2(accS[2*ks+1][2], accS[2*ks+1][3]);
#pragma unroll
            for (int pr = 0; pr < 4; pr++) {
                uint32_t r4[4];
                ldm_x4_trans(r4, smem_u32(&Vp[(ks*16 + vrow)*KSTR + pr*16 + vcol]));
                mma_f16(accO[2*pr],   ph, r4);
                mma_f16(accO[2*pr+1], ph, r4 + 2);
            }
        }
    }

    const int rloc = w*16 + gid;   // 0..127
    if (partial) {
        const int job = (bh*8 + (qt - 8))*2 + sp;
        float* pO = g_pO + (size_t)job*8192;
#pragma unroll
        for (int nt = 0; nt < 8; nt++) {
            const int col = nt*8 + tig*2;
            *(float2*)(pO + rloc*64 + col)     = make_float2(accO[nt][0], accO[nt][1]);
            *(float2*)(pO + (rloc+8)*64 + col) = make_float2(accO[nt][2], accO[nt][3]);
        }
        if (tig == 0) {
            float* pml = g_pml + (size_t)job*256;
            pml[rloc*2]       = m0;  pml[rloc*2 + 1]       = l0;
            pml[(rloc+8)*2]   = m1;  pml[(rloc+8)*2 + 1]   = l1;
        }
    } else {
        const float inv0 = 1.f / l0, inv1 = 1.f / l1;
        const int row0 = qt*128 + rloc;
        const size_t base0 = ((size_t)b*SEQ + row0)*DM + h*DH;
        const size_t base1 = base0 + (size_t)8*DM;
#pragma unroll
        for (int nt = 0; nt < 8; nt++) {
            const int d = nt*8 + tig*2;
            uint32_t hh, ll;
            split2(accO[nt][0]*inv0, accO[nt][1]*inv0, hh, ll);
            *(uint32_t*)(g_Oh + base0 + d) = hh;
            *(uint32_t*)(g_Ol + base0 + d) = ll;
            split2(accO[nt][2]*inv1, accO[nt][3]*inv1, hh, ll);
            *(uint32_t*)(g_Oh + base1 + d) = hh;
            *(uint32_t*)(g_Ol + base1 + d) = ll;
        }
    }
}

// ---------------- split-KV reduction (128-row tiles, m in log2 domain) ----------------
__global__ void __launch_bounds__(256) attn_reduce_kernel() {
    const int qi = blockIdx.x, h = blockIdx.y, b = blockIdx.z;   // qi 0..7 -> tile 8+qi
    const int t = threadIdx.x;
    const int r = t >> 1, c0 = (t & 1) * 32;                     // 128 rows x 2 half-rows
    const int jb = ((b*NH + h)*8 + qi)*2;

    const float* pml0 = g_pml + (size_t)jb*256;
    const float* pml1 = g_pml + (size_t)(jb+1)*256;
    const float m0 = pml0[r*2], l0 = pml0[r*2 + 1];
    const float m1 = pml1[r*2], l1 = pml1[r*2 + 1];
    const float M  = fmaxf(m0, m1);
    const float w0 = ex2f(m0 - M), w1 = ex2f(m1 - M);
    const float inv = 1.f / (l0*w0 + l1*w1);

    const float* A0 = g_pO + (size_t)jb*8192     + r*64 + c0;
    const float* A1 = g_pO + (size_t)(jb+1)*8192 + r*64 + c0;
    const int row = (8 + qi)*128 + r;
    __nv_bfloat16* oh = g_Oh + ((size_t)b*SEQ + row)*DM + h*DH + c0;
    __nv_bfloat16* ol = g_Ol + ((size_t)b*SEQ + row)*DM + h*DH + c0;

#pragma unroll
    for (int cc = 0; cc < 32; cc += 4) {
        float4 a0 = *(const float4*)(A0 + cc);
        float4 a1 = *(const float4*)(A1 + cc);
        float o0 = (a0.x*w0 + a1.x*w1)*inv;
        float o1 = (a0.y*w0 + a1.y*w1)*inv;
        float o2 = (a0.z*w0 + a1.z*w1)*inv;
        float o3 = (a0.w*w0 + a1.w*w1)*inv;
        uint32_t hh, ll;
        split2(o0, o1, hh, ll);
        *(uint32_t*)(oh + cc)     = hh; *(uint32_t*)(ol + cc)     = ll;
        split2(o2, o3, hh, ll);
        *(uint32_t*)(oh + cc + 2) = hh; *(uint32_t*)(ol + cc + 2) = ll;
    }
}

extern "C" void kernel_launch(void* const* d_in, const int* in_sizes, int n_in,
                              void* d_out, int out_size) {
    const float* x    = (const float*)d_in[0];
    const float* Wq   = (const float*)d_in[1];
    const float* Wk   = (const float*)d_in[2];
    const float* Wv   = (const float*)d_in[3];
    const float* Wo   = (const float*)d_in[4];
    const float* logc = (const float*)d_in[5];
    const float* logb = (const float*)d_in[6];
    if (in_sizes[0] != NB * SEQ * DM) {
        const float* xf = nullptr; const float* ws[4] = {}; const float* sc[2] = {};
        int nw = 0, ns = 0;
        for (int i = 0; i < n_in; i++) {
            if (in_sizes[i] == NB * SEQ * DM)          xf = (const float*)d_in[i];
            else if (in_sizes[i] == DM * DM && nw < 4) ws[nw++] = (const float*)d_in[i];
            else if (in_sizes[i] == 1 && ns < 2)       sc[ns++] = (const float*)d_in[i];
        }
        if (xf && nw == 4 && ns == 2) {
            x = xf; Wq = ws[0]; Wk = ws[1]; Wv = ws[2]; Wo = ws[3];
            logc = sc[0]; logb = sc[1];
        }
    }
    float* out = (float*)d_out;

    cudaFuncSetAttribute(attn_mma_kernel,    cudaFuncAttributeMaxDynamicSharedMemorySize, ATTN_SMEM);
    cudaFuncSetAttribute(mma_gemm_kernel<0>, cudaFuncAttributeMaxDynamicSharedMemorySize, GEMM_SMEM);
    cudaFuncSetAttribute(mma_gemm_kernel<1>, cudaFuncAttributeMaxDynamicSharedMemorySize, GEMM_SMEM);

    cvt_x_kernel<<<(MROWS*DM/4 + 255)/256, 256>>>(x, MROWS*DM);
    dim3 wgrid(DM*DM/4/256, 4);
    cvt_w_kernel<<<wgrid, 256>>>(Wq, Wk, Wv, Wo);

    dim3 pgrid(DM / 64, MROWS / 128, 3);
    mma_gemm_kernel<0><<<pgrid, 256, GEMM_SMEM>>>(nullptr);

    dim3 agrid(24, NH, NB);
    attn_mma_kernel<<<agrid, 256, ATTN_SMEM>>>(logc, logb);

    dim3 rgrid(8, NH, NB);
    attn_reduce_kernel<<<rgrid, 256>>>();

    dim3 ogrid(DM / 64, MROWS / 128, 1);
    mma_gemm_kernel<1><<<ogrid, 256, GEMM_SMEM>>>(out);
}

// round 17
// speedup vs baseline: 1.5754x; 1.5754x over previous
#include <cuda_runtime.h>
#include <cuda_bf16.h>
#include <cuda_fp16.h>
#include <math_constants.h>
#include <cstdint>

#define SEQ 2048
#define DM  512
#define NB  2
#define NH  8
#define DH  64
#define MROWS (NB*SEQ)   // 4096

// split activations, head-split layout [b][h][n][dh]
__device__ __align__(16) __nv_bfloat16 g_Qh[NB*NH*SEQ*DH], g_Ql[NB*NH*SEQ*DH];
__device__ __align__(16) __nv_bfloat16 g_Kh[NB*NH*SEQ*DH], g_Kl[NB*NH*SEQ*DH];
__device__ __align__(16) __half       g_Vh[NB*NH*SEQ*DH];
__device__ __align__(16) float        g_qn[NB*NH*SEQ], g_kn[NB*NH*SEQ];
// GEMM operands
__device__ __align__(16) __nv_bfloat16 g_xh[MROWS*DM], g_xl[MROWS*DM];
__device__ __align__(16) __nv_bfloat16 g_Wh[4*DM*DM],  g_Wl[4*DM*DM];
__device__ __align__(16) __nv_bfloat16 g_Oh[MROWS*DM], g_Ol[MROWS*DM];
// split-KV partial scratch
__device__ __align__(16) float g_pO[512*4096];
__device__ __align__(16) float g_pml[512*128];

#define LOG2E 1.4426950408889634f

// ---------------- helpers ----------------
__device__ __forceinline__ uint32_t smem_u32(const void* p) {
    uint32_t a;
    asm("{ .reg .u64 t; cvta.to.shared.u64 t, %1; cvt.u32.u64 %0, t; }" : "=r"(a) : "l"(p));
    return a;
}
__device__ __forceinline__ float ex2f(float x) {
    float y; asm("ex2.approx.f32 %0, %1;" : "=f"(y) : "f"(x)); return y;
}
#define CPA16(dst, src) asm volatile("cp.async.cg.shared.global [%0], [%1], 16;" :: "r"(dst), "l"(src) : "memory")
#define CP_COMMIT()     asm volatile("cp.async.commit_group;" ::: "memory")
#define CP_WAIT1()      asm volatile("cp.async.wait_group 1;" ::: "memory")

__device__ __forceinline__ void ldm_x4(uint32_t* r, uint32_t addr) {
    asm volatile("ldmatrix.sync.aligned.m8n8.x4.shared.b16 {%0,%1,%2,%3}, [%4];"
                 : "=r"(r[0]), "=r"(r[1]), "=r"(r[2]), "=r"(r[3]) : "r"(addr));
}
__device__ __forceinline__ void ldm_x4_trans(uint32_t* r, uint32_t addr) {
    asm volatile("ldmatrix.sync.aligned.m8n8.x4.trans.shared.b16 {%0,%1,%2,%3}, [%4];"
                 : "=r"(r[0]), "=r"(r[1]), "=r"(r[2]), "=r"(r[3]) : "r"(addr));
}
__device__ __forceinline__ void mma_bf16(float* d, const uint32_t* a, const uint32_t* b) {
    asm volatile("mma.sync.aligned.m16n8k16.row.col.f32.bf16.bf16.f32 "
                 "{%0,%1,%2,%3}, {%4,%5,%6,%7}, {%8,%9}, {%0,%1,%2,%3};"
                 : "+f"(d[0]), "+f"(d[1]), "+f"(d[2]), "+f"(d[3])
                 : "r"(a[0]), "r"(a[1]), "r"(a[2]), "r"(a[3]), "r"(b[0]), "r"(b[1]));
}
__device__ __forceinline__ void mma_f16(float* d, const uint32_t* a, const uint32_t* b) {
    asm volatile("mma.sync.aligned.m16n8k16.row.col.f32.f16.f16.f32 "
                 "{%0,%1,%2,%3}, {%4,%5,%6,%7}, {%8,%9}, {%0,%1,%2,%3};"
                 : "+f"(d[0]), "+f"(d[1]), "+f"(d[2]), "+f"(d[3])
                 : "r"(a[0]), "r"(a[1]), "r"(a[2]), "r"(a[3]), "r"(b[0]), "r"(b[1]));
}
__device__ __forceinline__ void split2(float a, float b, uint32_t& h, uint32_t& l) {
    __nv_bfloat16 ha = __float2bfloat16(a), hb = __float2bfloat16(b);
    __nv_bfloat16 la = __float2bfloat16(a - __bfloat162float(ha));
    __nv_bfloat16 lb = __float2bfloat16(b - __bfloat162float(hb));
    __nv_bfloat162 H; H.x = ha; H.y = hb;
    __nv_bfloat162 L; L.x = la; L.y = lb;
    h = *(uint32_t*)&H; l = *(uint32_t*)&L;
}
__device__ __forceinline__ uint32_t packh2(float a, float b) {
    __half2 h = __floats2half2_rn(a, b);
    return *(uint32_t*)&h;
}

// ---------------- conversions ----------------
__global__ void __launch_bounds__(256) cvt_x_kernel(const float* __restrict__ src, int n) {
    int i = (blockIdx.x * 256 + threadIdx.x) * 4;
    if (i >= n) return;
    float4 v = *(const float4*)(src + i);
    float vv[4] = {v.x, v.y, v.z, v.w};
#pragma unroll
    for (int k = 0; k < 4; k++) {
        __nv_bfloat16 h = __float2bfloat16(vv[k]);
        g_xh[i + k] = h;
        g_xl[i + k] = __float2bfloat16(vv[k] - __bfloat162float(h));
    }
}
__global__ void __launch_bounds__(256) cvt_w_kernel(const float* __restrict__ w0,
                                                    const float* __restrict__ w1,
                                                    const float* __restrict__ w2,
                                                    const float* __restrict__ w3) {
    const int z = blockIdx.y;
    const float* src = (z == 0) ? w0 : (z == 1) ? w1 : (z == 2) ? w2 : w3;
    int i = (blockIdx.x * 256 + threadIdx.x) * 4;
    __nv_bfloat16* dh = g_Wh + (size_t)z * DM * DM;
    __nv_bfloat16* dl = g_Wl + (size_t)z * DM * DM;
    float4 v = *(const float4*)(src + i);
    float vv[4] = {v.x, v.y, v.z, v.w};
#pragma unroll
    for (int k = 0; k < 4; k++) {
        __nv_bfloat16 h = __float2bfloat16(vv[k]);
        dh[i + k] = h;
        dl[i + k] = __float2bfloat16(vv[k] - __bfloat162float(h));
    }
}

// ---------------- split-bf16 GEMM via mma.sync, 128x64 tile, cp.async 2-stage ----------------
#define ASTR 40
#define G_A_BUF (128*ASTR*2)               // 10240 B
#define G_B_BUF (64*ASTR*2)                // 5120 B
#define GEMM_STAGE_B (2*G_A_BUF + 2*G_B_BUF)  // 30720 B
#define GEMM_SMEM    (2*GEMM_STAGE_B)      // 61440 B

template<int MODE>
__global__ void __launch_bounds__(256) mma_gemm_kernel(float* __restrict__ outp) {
    extern __shared__ __align__(16) char gsm[];
    const int t = threadIdx.x, lane = t & 31, w = t >> 5;
    const int wm = w & 3, wn = w >> 2;           // warp tile 32x32
    const int m0 = blockIdx.y * 128, j0 = blockIdx.x * 64;
    const int wsel = (MODE == 0) ? (int)blockIdx.z : 3;

    const __nv_bfloat16* Ahp = (MODE == 0) ? g_xh : g_Oh;
    const __nv_bfloat16* Alp = (MODE == 0) ? g_xl : g_Ol;
    const __nv_bfloat16* Whp = g_Wh + (size_t)wsel * DM * DM;
    const __nv_bfloat16* Wlp = g_Wl + (size_t)wsel * DM * DM;

    const uint32_t smb = smem_u32(gsm);

    float acc[2][4][4];
#pragma unroll
    for (int mt = 0; mt < 2; mt++)
#pragma unroll
        for (int nt = 0; nt < 4; nt++)
#pragma unroll
            for (int e = 0; e < 4; e++) acc[mt][nt][e] = 0.f;

    const int arow = wm*32 + (lane & 15);
    const int boff = ((lane >> 4) & 1) * 8;
    const int brow = wn*32 + (lane & 7) + ((lane >> 4) & 1) * 8;
    const int bcol = ((lane >> 3) & 1) * 8;

    // prologue: slab 0 -> stage 0
    {
#pragma unroll
        for (int p = 0; p < 2; p++) {
            int id = t + 256 * p;
            int r = id >> 2, cc = id & 3;
            uint32_t off = (uint32_t)(r * ASTR * 2 + cc * 16);
            const size_t ga = (size_t)(m0 + r) * DM + cc*8;
            CPA16(smb + off,           Ahp + ga);
            CPA16(smb + G_A_BUF + off, Alp + ga);
        }
        {
            int r = t >> 2, cc = t & 3;
            uint32_t off = (uint32_t)(r * ASTR * 2 + cc * 16);
            const size_t gb = (size_t)(j0 + r) * DM + cc*8;
            CPA16(smb + 2*G_A_BUF + off,           Whp + gb);
            CPA16(smb + 2*G_A_BUF + G_B_BUF + off, Wlp + gb);
        }
        CP_COMMIT();
    }

    for (int s = 0; s < DM/32; s++) {
        const int st = s & 1;
        __syncthreads();
        if (s + 1 < DM/32) {
            const uint32_t base = smb + (st ^ 1) * GEMM_STAGE_B;
#pragma unroll
            for (int p = 0; p < 2; p++) {
                int id = t + 256 * p;
                int r = id >> 2, cc = id & 3;
                uint32_t off = (uint32_t)(r * ASTR * 2 + cc * 16);
                const size_t ga = (size_t)(m0 + r) * DM + (s+1)*32 + cc*8;
                CPA16(base + off,           Ahp + ga);
                CPA16(base + G_A_BUF + off, Alp + ga);
            }
            {
                int r = t >> 2, cc = t & 3;
                uint32_t off = (uint32_t)(r * ASTR * 2 + cc * 16);
                const size_t gb = (size_t)(j0 + r) * DM + (s+1)*32 + cc*8;
                CPA16(base + 2*G_A_BUF + off,           Whp + gb);
                CPA16(base + 2*G_A_BUF + G_B_BUF + off, Wlp + gb);
            }
        }
        CP_COMMIT();
        CP_WAIT1();
        __syncthreads();

        const __nv_bfloat16* sAh = (const __nv_bfloat16*)(gsm + st * GEMM_STAGE_B);
        const __nv_bfloat16* sAl = sAh + 128*ASTR;
        const __nv_bfloat16* sBh = sAl + 128*ASTR;
        const __nv_bfloat16* sBl = sBh + 64*ASTR;

#pragma unroll
        for (int ks = 0; ks < 2; ks++) {
            uint32_t ah[2][4], al[2][4];
#pragma unroll
            for (int mt = 0; mt < 2; mt++) {
                ldm_x4(ah[mt], smem_u32(&sAh[(arow + mt*16)*ASTR + ks*16 + boff]));
                ldm_x4(al[mt], smem_u32(&sAl[(arow + mt*16)*ASTR + ks*16 + boff]));
            }
            uint32_t bh[4][2], bl[4][2];
#pragma unroll
            for (int pr = 0; pr < 2; pr++) {
                uint32_t r4[4];
                ldm_x4(r4, smem_u32(&sBh[(brow + pr*16)*ASTR + ks*16 + bcol]));
                bh[2*pr][0] = r4[0]; bh[2*pr][1] = r4[1];
                bh[2*pr+1][0] = r4[2]; bh[2*pr+1][1] = r4[3];
                ldm_x4(r4, smem_u32(&sBl[(brow + pr*16)*ASTR + ks*16 + bcol]));
                bl[2*pr][0] = r4[0]; bl[2*pr][1] = r4[1];
                bl[2*pr+1][0] = r4[2]; bl[2*pr+1][1] = r4[3];
            }
#pragma unroll
            for (int mt = 0; mt < 2; mt++)
#pragma unroll
                for (int nt = 0; nt < 4; nt++) {
                    mma_bf16(acc[mt][nt], ah[mt], bh[nt]);
                    mma_bf16(acc[mt][nt], ah[mt], bl[nt]);
                    mma_bf16(acc[mt][nt], al[mt], bh[nt]);
                }
        }
    }

    const int gid = lane >> 2, tig = lane & 3;
#pragma unroll
    for (int mt = 0; mt < 2; mt++) {
#pragma unroll
        for (int nt = 0; nt < 4; nt++) {
            const int mrow = m0 + wm*32 + mt*16 + gid;
            const int jcol = j0 + wn*32 + nt*8 + tig*2;
            if (MODE == 1) {
                *(float2*)(outp + (size_t)mrow * DM + jcol)     = make_float2(acc[mt][nt][0], acc[mt][nt][1]);
                *(float2*)(outp + (size_t)(mrow+8) * DM + jcol) = make_float2(acc[mt][nt][2], acc[mt][nt][3]);
            } else {
                const int hh = j0 >> 6, d = jcol & (DH-1);
                const int b0r = mrow >> 11, n0r = mrow & (SEQ-1);
                const size_t base = ((size_t)(b0r*NH + hh)*SEQ + n0r)*DH + d;
                if (blockIdx.z == 2) {          // V: single fp16
                    *(uint32_t*)(g_Vh + base)        = packh2(acc[mt][nt][0], acc[mt][nt][1]);
                    *(uint32_t*)(g_Vh + base + 8*DH) = packh2(acc[mt][nt][2], acc[mt][nt][3]);
                } else {
                    __nv_bfloat16* dsh = (blockIdx.z == 0) ? g_Qh : g_Kh;
                    __nv_bfloat16* dsl = (blockIdx.z == 0) ? g_Ql : g_Kl;
                    uint32_t ph_, pl_;
                    split2(acc[mt][nt][0], acc[mt][nt][1], ph_, pl_);
                    *(uint32_t*)(dsh + base) = ph_;
                    *(uint32_t*)(dsl + base) = pl_;
                    split2(acc[mt][nt][2], acc[mt][nt][3], ph_, pl_);
                    *(uint32_t*)(dsh + base + 8*DH) = ph_;
                    *(uint32_t*)(dsl + base + 8*DH) = pl_;
                }
            }
        }
    }

    // ---- fused exact row norms for Q (z=0) and K (z=1) ----
    if (MODE == 0 && blockIdx.z < 2) {
        float* np = (blockIdx.z == 0) ? g_qn : g_kn;
        float* spart = (float*)gsm;
        __syncthreads();
#pragma unroll
        for (int mt = 0; mt < 2; mt++) {
            float s0 = 0.f, s1 = 0.f;
#pragma unroll
            for (int nt = 0; nt < 4; nt++) {
                s0 = fmaf(acc[mt][nt][0], acc[mt][nt][0], fmaf(acc[mt][nt][1], acc[mt][nt][1], s0));
                s1 = fmaf(acc[mt][nt][2], acc[mt][nt][2], fmaf(acc[mt][nt][3], acc[mt][nt][3], s1));
            }
            s0 += __shfl_xor_sync(0xffffffffu, s0, 1);
            s0 += __shfl_xor_sync(0xffffffffu, s0, 2);
            s1 += __shfl_xor_sync(0xffffffffu, s1, 1);
            s1 += __shfl_xor_sync(0xffffffffu, s1, 2);
            if (tig == 0) {
                spart[((w*2 + mt)*2 + 0)*8 + gid] = s0;
                spart[((w*2 + mt)*2 + 1)*8 + gid] = s1;
            }
        }
        __syncthreads();
        if (w < 4) {
            const int mt = lane >> 4, half = (lane >> 3) & 1, g8 = lane & 7;
            const float s = spart[((w*2 + mt)*2 + half)*8 + g8]
                          + spart[(((w+4)*2 + mt)*2 + half)*8 + g8];
            const int mrow = m0 + w*32 + mt*16 + half*8 + g8;
            const int hh = j0 >> 6;
            const int b0r = mrow >> 11, n0r = mrow & (SEQ-1);
            np[(size_t)(b0r*NH + hh)*SEQ + n0r] = s;
        }
    }
}

// ---------------- mma.sync hyperbolic flash attention ----------------
// log2-domain softmax; V single fp16; fused double-buffered K/V/kn stage.
#define KSTR 72
#define TILE_B (64*KSTR*2)                 // 9216 B
#define QSZ    (2*TILE_B)                  // 18432 B (Qh, Ql)
#define STAGE_B (3*TILE_B + 256)           // Kh, Kl, V, kn = 27904 B
#define ATTN_SMEM (QSZ + 2*STAGE_B)        // 74240 B
#define PRUNE_MARGIN 29.0f                 // log2 units (~20 nats)

__global__ void __launch_bounds__(128, 3) attn_mma_kernel(const float* __restrict__ p_logc,
                                                          const float* __restrict__ p_logb) {
    extern __shared__ __align__(16) char smraw[];
    __nv_bfloat16* Qh = (__nv_bfloat16*)smraw;
    __nv_bfloat16* Ql = (__nv_bfloat16*)(smraw + TILE_B);
    const uint32_t smb = smem_u32(smraw);

    const int t = threadIdx.x, lane = t & 31, w = t >> 5;
    const int jx = (int)blockIdx.x;
    const int h = blockIdx.y, b = blockIdx.z;
    const int bh = b*NH + h;

    int qt, k0, k1, sp;
    bool partial;
    if (jx < 32) {
        qt = 31 - (jx >> 1);
        sp = jx & 1;
        const int mid = (qt + 1) >> 1;
        k0 = sp ? mid : 0;
        k1 = sp ? (qt + 1) : mid;
        partial = true;
    } else {
        qt = 47 - jx; k0 = 0; k1 = qt + 1; sp = 0; partial = false;
    }
    const int nk = k1 - k0;

    const float c    = log1pf(__expf(*p_logc));
    const float beta = log1pf(__expf(*p_logb)) + 0.5f;
    const float nbl  = -beta * LOG2E;          // log2-domain score scale

    const int gid = lane >> 2, tig = lane & 3;

    const size_t qoff = ((size_t)bh*SEQ + qt*64) * DH;
#pragma unroll
    for (int p = 0; p < 4; p++) {
        int id = t + 128*p;
        int r = id >> 3, cc = id & 7;
        *(uint4*)&Qh[r*KSTR + cc*8] = *(const uint4*)(g_Qh + qoff + r*64 + cc*8);
        *(uint4*)&Ql[r*KSTR + cc*8] = *(const uint4*)(g_Ql + qoff + r*64 + cc*8);
    }
    const float qn0 = g_qn[(size_t)bh*SEQ + qt*64 + w*16 + gid];
    const float qn1 = g_qn[(size_t)bh*SEQ + qt*64 + w*16 + gid + 8];

    const int arow  = w*16 + (lane & 15);
    const int acsel = ((lane >> 4) & 1) * 8;
    const int brow  = (lane & 7) + ((lane >> 4) & 1) * 8;
    const int bcol  = ((lane >> 3) & 1) * 8;

    float accO[8][4];
#pragma unroll
    for (int nt = 0; nt < 8; nt++)
#pragma unroll
        for (int e = 0; e < 4; e++) accO[nt][e] = 0.f;
    float m0 = -CUDART_INF_F, m1 = -CUDART_INF_F, l0 = 0.f, l1 = 0.f;

    // prologue: tile (k1-1) -> stage 0 (diagonal-first order)
    {
        const size_t koff = ((size_t)bh*SEQ + (k1-1)*64) * DH;
        const uint32_t base = smb + QSZ;
#pragma unroll
        for (int p = 0; p < 4; p++) {
            int id = t + 128*p;
            int r = id >> 3, cc = id & 7;
            uint32_t off = (uint32_t)(r*KSTR*2 + cc*16);
            CPA16(base + off,            g_Kh + koff + r*64 + cc*8);
            CPA16(base + TILE_B + off,   g_Kl + koff + r*64 + cc*8);
            CPA16(base + 2*TILE_B + off, g_Vh + koff + r*64 + cc*8);
        }
        if (t < 16) CPA16(base + 3*TILE_B + t*16, g_kn + (size_t)bh*SEQ + (k1-1)*64 + t*4);
        CP_COMMIT();
    }

    for (int i = 0; i < nk; i++) {
        const int kt = k1 - 1 - i;
        const int st = i & 1;
        __syncthreads();

        if (i + 1 < nk) {
            const size_t koff = ((size_t)bh*SEQ + (kt-1)*64) * DH;
            const uint32_t base = smb + QSZ + (st ^ 1) * STAGE_B;
#pragma unroll
            for (int p = 0; p < 4; p++) {
                int id = t + 128*p;
                int r = id >> 3, cc = id & 7;
                uint32_t off = (uint32_t)(r*KSTR*2 + cc*16);
                CPA16(base + off,            g_Kh + koff + r*64 + cc*8);
                CPA16(base + TILE_B + off,   g_Kl + koff + r*64 + cc*8);
                CPA16(base + 2*TILE_B + off, g_Vh + koff + r*64 + cc*8);
            }
            if (t < 16) CPA16(base + 3*TILE_B + t*16, g_kn + (size_t)bh*SEQ + (kt-1)*64 + t*4);
        }
        CP_COMMIT();
        CP_WAIT1();
        __syncthreads();

        const char* stg = smraw + QSZ + st*STAGE_B;
        const __nv_bfloat16* Kh = (const __nv_bfloat16*)stg;
        const __nv_bfloat16* Kl = (const __nv_bfloat16*)(stg + TILE_B);
        const __half*        Vp = (const __half*)(stg + 2*TILE_B);
        const float*         kn = (const float*)(stg + 3*TILE_B);

        // ---- S = Q K^T ----
        float accS[8][4];
#pragma unroll
        for (int nt = 0; nt < 8; nt++)
#pragma unroll
            for (int e = 0; e < 4; e++) accS[nt][e] = 0.f;
#pragma unroll
        for (int ks = 0; ks < 4; ks++) {
            uint32_t ah[4], al[4];
            ldm_x4(ah, smem_u32(&Qh[arow*KSTR + ks*16 + acsel]));
            ldm_x4(al, smem_u32(&Ql[arow*KSTR + ks*16 + acsel]));
            uint32_t kbh[8][2], kbl[8][2];
#pragma unroll
            for (int pr = 0; pr < 4; pr++) {
                uint32_t r4[4];
                ldm_x4(r4, smem_u32(&Kh[(brow + pr*16)*KSTR + ks*16 + bcol]));
                kbh[2*pr][0] = r4[0]; kbh[2*pr][1] = r4[1];
                kbh[2*pr+1][0] = r4[2]; kbh[2*pr+1][1] = r4[3];
                ldm_x4(r4, smem_u32(&Kl[(brow + pr*16)*KSTR + ks*16 + bcol]));
                kbl[2*pr][0] = r4[0]; kbl[2*pr][1] = r4[1];
                kbl[2*pr+1][0] = r4[2]; kbl[2*pr+1][1] = r4[3];
            }
#pragma unroll
            for (int nt = 0; nt < 8; nt++) {
                mma_bf16(accS[nt], ah, kbh[nt]);
                mma_bf16(accS[nt], ah, kbl[nt]);
                mma_bf16(accS[nt], al, kbh[nt]);
            }
        }

        // ---- log2-domain scores ----
#pragma unroll
        for (int nt = 0; nt < 8; nt++) {
            const int lc = nt*8 + tig*2;
            const float kn0 = kn[lc], kn1 = kn[lc + 1];
            float sv[4] = {accS[nt][0], accS[nt][1], accS[nt][2], accS[nt][3]};
            float qq[4] = {qn0, qn0, qn1, qn1};
            float kk[4] = {kn0, kn1, kn0, kn1};
#pragma unroll
            for (int e = 0; e < 4; e++) {
                float a    = qq[e] + kk[e];
                float diff = fmaxf(fmaf(-2.f, sv[e], a), 1e-8f);
                float prod = diff * fmaf(c, a, 1.f);
                accS[nt][e] = nbl * (prod * rsqrtf(prod));
            }
        }
        // ---- causal mask: only the diagonal tile ----
        if (kt == qt) {
            const int grow0 = qt*64 + w*16 + gid, grow1 = grow0 + 8;
#pragma unroll
            for (int nt = 0; nt < 8; nt++) {
                const int gc0 = kt*64 + nt*8 + tig*2, gc1 = gc0 + 1;
                accS[nt][0] = (gc0 <= grow0) ? accS[nt][0] : -CUDART_INF_F;
                accS[nt][1] = (gc1 <= grow0) ? accS[nt][1] : -CUDART_INF_F;
                accS[nt][2] = (gc0 <= grow1) ? accS[nt][2] : -CUDART_INF_F;
                accS[nt][3] = (gc1 <= grow1) ? accS[nt][3] : -CUDART_INF_F;
            }
        }

        // ---- row maxes ----
        float rmax0 = -CUDART_INF_F, rmax1 = -CUDART_INF_F;
#pragma unroll
        for (int nt = 0; nt < 8; nt++) {
            rmax0 = fmaxf(rmax0, fmaxf(accS[nt][0], accS[nt][1]));
            rmax1 = fmaxf(rmax1, fmaxf(accS[nt][2], accS[nt][3]));
        }
        rmax0 = fmaxf(rmax0, __shfl_xor_sync(0xffffffffu, rmax0, 1));
        rmax0 = fmaxf(rmax0, __shfl_xor_sync(0xffffffffu, rmax0, 2));
        rmax1 = fmaxf(rmax1, __shfl_xor_sync(0xffffffffu, rmax1, 1));
        rmax1 = fmaxf(rmax1, __shfl_xor_sync(0xffffffffu, rmax1, 2));

        // ---- prune (strict > so all -inf rows skip safely) ----
        const bool keep = (rmax0 > m0 - PRUNE_MARGIN) || (rmax1 > m1 - PRUNE_MARGIN);
        if (!__any_sync(0xffffffffu, keep)) continue;

        // ---- rescale only if max advanced ----
        {
            const float mn0 = fmaxf(m0, rmax0), mn1 = fmaxf(m1, rmax1);
            const bool ch = (mn0 != m0) || (mn1 != m1);
            if (__any_sync(0xffffffffu, ch)) {
                const float sc0 = ex2f(m0 - mn0), sc1 = ex2f(m1 - mn1);
#pragma unroll
                for (int nt = 0; nt < 8; nt++) {
                    accO[nt][0] *= sc0; accO[nt][1] *= sc0;
                    accO[nt][2] *= sc1; accO[nt][3] *= sc1;
                }
                l0 *= sc0; l1 *= sc1;
                m0 = mn0; m1 = mn1;
            }
        }

        // ---- weights (raw ex2) ----
        float rs0 = 0.f, rs1 = 0.f;
#pragma unroll
        for (int nt = 0; nt < 8; nt++) {
            float w0 = ex2f(accS[nt][0] - m0);
            float w1 = ex2f(accS[nt][1] - m0);
            float w2 = ex2f(accS[nt][2] - m1);
            float w3 = ex2f(accS[nt][3] - m1);
            accS[nt][0] = w0; accS[nt][1] = w1; accS[nt][2] = w2; accS[nt][3] = w3;
            rs0 += w0 + w1; rs1 += w2 + w3;
        }
        rs0 += __shfl_xor_sync(0xffffffffu, rs0, 1);
        rs0 += __shfl_xor_sync(0xffffffffu, rs0, 2);
        rs1 += __shfl_xor_sync(0xffffffffu, rs1, 1);
        rs1 += __shfl_xor_sync(0xffffffffu, rs1, 2);
        l0 += rs0; l1 += rs1;

        // ---- O += P V (single fp16 V) ----
        const int vrow = ((lane >> 3) & 1) * 8 + (lane & 7);
        const int vcol = ((lane >> 4) & 1) * 8;
#pragma unroll
        for (int ks = 0; ks < 4; ks++) {
            uint32_t ph[4];
            ph[0] = packh2(accS[2*ks][0],   accS[2*ks][1]);
            ph[1] = packh2(accS[2*ks][2],   accS[2*ks][3]);
            ph[2] = packh2(accS[2*ks+1][0], accS[2*ks+1][1]);
            ph[3] = packh2(accS[2*ks+1][2], accS[2*ks+1][3]);
            uint32_t vb[8][2];
#pragma unroll
            for (int pr = 0; pr < 4; pr++) {
                uint32_t r4[4];
                ldm_x4_trans(r4, smem_u32(&Vp[(ks*16 + vrow)*KSTR + pr*16 + vcol]));
                vb[2*pr][0] = r4[0]; vb[2*pr][1] = r4[1];
                vb[2*pr+1][0] = r4[2]; vb[2*pr+1][1] = r4[3];
            }
#pragma unroll
            for (int nt = 0; nt < 8; nt++)
                mma_f16(accO[nt], ph, vb[nt]);
        }
    }

    const int rloc = w*16 + gid;
    if (partial) {
        const int job = ((bh)*16 + (qt - 16))*2 + sp;
        float* pO = g_pO + (size_t)job*4096;
#pragma unroll
        for (int nt = 0; nt < 8; nt++) {
            const int col = nt*8 + tig*2;
            *(float2*)(pO + rloc*64 + col)     = make_float2(accO[nt][0], accO[nt][1]);
            *(float2*)(pO + (rloc+8)*64 + col) = make_float2(accO[nt][2], accO[nt][3]);
        }
        if (tig == 0) {
            float* pml = g_pml + (size_t)job*128;
            pml[rloc*2]       = m0;  pml[rloc*2 + 1]       = l0;
            pml[(rloc+8)*2]   = m1;  pml[(rloc+8)*2 + 1]   = l1;
        }
    } else {
        const float inv0 = 1.f / l0, inv1 = 1.f / l1;
        const int row0 = qt*64 + rloc;
        const size_t base0 = ((size_t)b*SEQ + row0)*DM + h*DH;
        const size_t base1 = base0 + (size_t)8*DM;
#pragma unroll
        for (int nt = 0; nt < 8; nt++) {
            const int d = nt*8 + tig*2;
            uint32_t hh, ll;
            split2(accO[nt][0]*inv0, accO[nt][1]*inv0, hh, ll);
            *(uint32_t*)(g_Oh + base0 + d) = hh;
            *(uint32_t*)(g_Ol + base0 + d) = ll;
            split2(accO[nt][2]*inv1, accO[nt][3]*inv1, hh, ll);
            *(uint32_t*)(g_Oh + base1 + d) = hh;
            *(uint32_t*)(g_Ol + base1 + d) = ll;
        }
    }
}

// ---------------- split-KV reduction (m is log2-domain) ----------------
__global__ void __launch_bounds__(256) attn_reduce_kernel() {
    const int qi = blockIdx.x, h = blockIdx.y, b = blockIdx.z;
    const int t = threadIdx.x;
    const int r = t >> 2, c0 = (t & 3) * 16;
    const int jb = ((b*NH + h)*16 + qi)*2;

    const float* pml0 = g_pml + (size_t)jb*128;
    const float* pml1 = g_pml + (size_t)(jb+1)*128;
    const float m0 = pml0[r*2], l0 = pml0[r*2 + 1];
    const float m1 = pml1[r*2], l1 = pml1[r*2 + 1];
    const float M  = fmaxf(m0, m1);
    const float w0 = ex2f(m0 - M), w1 = ex2f(m1 - M);
    const float inv = 1.f / (l0*w0 + l1*w1);

    const float* A0 = g_pO + (size_t)jb*4096     + r*64 + c0;
    const float* A1 = g_pO + (size_t)(jb+1)*4096 + r*64 + c0;
    const int row = (16 + qi)*64 + r;
    __nv_bfloat16* oh = g_Oh + ((size_t)b*SEQ + row)*DM + h*DH + c0;
    __nv_bfloat16* ol = g_Ol + ((size_t)b*SEQ + row)*DM + h*DH + c0;

#pragma unroll
    for (int cc = 0; cc < 16; cc += 4) {
        float4 a0 = *(const float4*)(A0 + cc);
        float4 a1 = *(const float4*)(A1 + cc);
        float o0 = (a0.x*w0 + a1.x*w1)*inv;
        float o1 = (a0.y*w0 + a1.y*w1)*inv;
        float o2 = (a0.z*w0 + a1.z*w1)*inv;
        float o3 = (a0.w*w0 + a1.w*w1)*inv;
        uint32_t hh, ll;
        split2(o0, o1, hh, ll);
        *(uint32_t*)(oh + cc)     = hh; *(uint32_t*)(ol + cc)     = ll;
        split2(o2, o3, hh, ll);
        *(uint32_t*)(oh + cc + 2) = hh; *(uint32_t*)(ol + cc + 2) = ll;
    }
}

extern "C" void kernel_launch(void* const* d_in, const int* in_sizes, int n_in,
                              void* d_out, int out_size) {
    const float* x    = (const float*)d_in[0];
    const float* Wq   = (const float*)d_in[1];
    const float* Wk   = (const float*)d_in[2];
    const float* Wv   = (const float*)d_in[3];
    const float* Wo   = (const float*)d_in[4];
    const float* logc = (const float*)d_in[5];
    const float* logb = (const float*)d_in[6];
    if (in_sizes[0] != NB * SEQ * DM) {
        const float* xf = nullptr; const float* ws[4] = {}; const float* sc[2] = {};
        int nw = 0, ns = 0;
        for (int i = 0; i < n_in; i++) {
            if (in_sizes[i] == NB * SEQ * DM)          xf = (const float*)d_in[i];
            else if (in_sizes[i] == DM * DM && nw < 4) ws[nw++] = (const float*)d_in[i];
            else if (in_sizes[i] == 1 && ns < 2)       sc[ns++] = (const float*)d_in[i];
        }
        if (xf && nw == 4 && ns == 2) {
            x = xf; Wq = ws[0]; Wk = ws[1]; Wv = ws[2]; Wo = ws[3];
            logc = sc[0]; logb = sc[1];
        }
    }
    float* out = (float*)d_out;

    cudaFuncSetAttribute(attn_mma_kernel,    cudaFuncAttributeMaxDynamicSharedMemorySize, ATTN_SMEM);
    cudaFuncSetAttribute(mma_gemm_kernel<0>, cudaFuncAttributeMaxDynamicSharedMemorySize, GEMM_SMEM);
    cudaFuncSetAttribute(mma_gemm_kernel<1>, cudaFuncAttributeMaxDynamicSharedMemorySize, GEMM_SMEM);

    cvt_x_kernel<<<(MROWS*DM/4 + 255)/256, 256>>>(x, MROWS*DM);
    dim3 wgrid(DM*DM/4/256, 4);
    cvt_w_kernel<<<wgrid, 256>>>(Wq, Wk, Wv, Wo);

    dim3 pgrid(DM / 64, MROWS / 128, 3);
    mma_gemm_kernel<0><<<pgrid, 256, GEMM_SMEM>>>(nullptr);

    dim3 agrid(48, NH, NB);
    attn_mma_kernel<<<agrid, 128, ATTN_SMEM>>>(logc, logb);

    dim3 rgrid(16, NH, NB);
    attn_reduce_kernel<<<rgrid, 256>>>();

    dim3 ogrid(DM / 64, MROWS / 128, 1);
    mma_gemm_kernel<1><<<ogrid, 256, GEMM_SMEM>>>(out);
}